// round 11
// baseline (speedup 1.0000x reference)
#include <cuda_runtime.h>
#include <cuda_fp16.h>
#include <cstdint>

#define N_ROWS   10000
#define NPAD     10112          // padded for HnT tiles (10112 = 79*128)
#define D_IN     128
#define HID      32
#define EMB      16
#define NJT      79             // ceil(10000/128) column tiles
#define BM       40             // rows per CTA tile (50 * 40 = 2000 strip rows)
#define BN       128            // cols per CTA tile
#define SROWS    2000           // rows per L2 strip (5 strips)
#define NSTRIP   5
#define JSTRIPS  16             // 16 * 50 = 800 CTAs/launch <= 888 slots @ occ6

typedef unsigned long long ull;
struct __align__(16) ull2_t { ull x, y; };

// ---------------- static device scratch (no runtime allocations) ----------------
__device__ __align__(16) float g_Hn  [NPAD * EMB];       // normalized embeddings, row-major
__device__ __align__(16) float g_HnTs[EMB * NPAD];       // transposed, pre-scaled by kB
__device__ __align__(16) float g_Zpart[JSTRIPS * SROWS];
__device__ __align__(16) __half g_u[(size_t)SROWS * N_ROWS];  // 40MB fp16 u' strip (L2-resident)

// ---------------- f32x2 helpers ----------------
__device__ __forceinline__ ull f2pk(float lo, float hi) {
    ull r; asm("mov.b64 %0, {%1, %2};" : "=l"(r) : "f"(lo), "f"(hi)); return r;
}
__device__ __forceinline__ void f2up(ull v, float& lo, float& hi) {
    asm("mov.b64 {%0, %1}, %2;" : "=f"(lo), "=f"(hi) : "l"(v));
}
__device__ __forceinline__ ull ffma2(ull a, ull b, ull c) {
    ull d; asm("fma.rn.f32x2 %0, %1, %2, %3;" : "=l"(d) : "l"(a), "l"(b), "l"(c)); return d;
}

// ======================================================================
// Kernel 1: encoder.  H = relu(X@W1 + b1)@W2 + b2 ; Hn = H / max(||H||,1e-12)
// ======================================================================
__global__ void __launch_bounds__(256) encoder_kernel(
    const float* __restrict__ X, const float* __restrict__ W1,
    const float* __restrict__ b1, const float* __restrict__ W2,
    const float* __restrict__ b2, float* __restrict__ Hout,
    const float* __restrict__ p_log_tau, const float* __restrict__ p_raw_alpha)
{
    __shared__ float sW1[D_IN * HID];
    __shared__ float sW2[HID * EMB];
    __shared__ float sb1[HID];
    __shared__ float sb2[EMB];
    __shared__ float sX[8][D_IN];
    __shared__ float sH1[8][HID];

    const int tid = threadIdx.x;
    for (int i = tid; i < D_IN * HID; i += 256) sW1[i] = W1[i];
    for (int i = tid; i < HID * EMB;  i += 256) sW2[i] = W2[i];
    if (tid < HID) sb1[tid] = b1[tid];
    if (tid < EMB) sb2[tid] = b2[tid];
    __syncthreads();

    const int w    = tid >> 5;
    const int lane = tid & 31;
    const int row  = blockIdx.x * 8 + w;
    if (row >= NPAD) return;

    if (row >= N_ROWS) {
        if (lane < EMB) {
            g_Hn  [row * EMB + lane]  = 0.f;
            g_HnTs[lane * NPAD + row] = 0.f;
        }
        return;
    }

    #pragma unroll
    for (int q = 0; q < 4; ++q) sX[w][lane + 32 * q] = X[(size_t)row * D_IN + lane + 32 * q];
    __syncwarp();

    float s0 = sb1[lane], s1 = 0.f, s2 = 0.f, s3 = 0.f;
    #pragma unroll
    for (int k = 0; k < D_IN; k += 4) {
        s0 = fmaf(sX[w][k    ], sW1[(k    ) * HID + lane], s0);
        s1 = fmaf(sX[w][k + 1], sW1[(k + 1) * HID + lane], s1);
        s2 = fmaf(sX[w][k + 2], sW1[(k + 2) * HID + lane], s2);
        s3 = fmaf(sX[w][k + 3], sW1[(k + 3) * HID + lane], s3);
    }
    float h1 = fmaxf((s0 + s1) + (s2 + s3), 0.f);
    sH1[w][lane] = h1;
    __syncwarp();

    const int e = lane & 15;
    float t0 = sb2[e], t1 = 0.f;
    #pragma unroll
    for (int u = 0; u < HID; u += 2) {
        t0 = fmaf(sH1[w][u    ], sW2[(u    ) * EMB + e], t0);
        t1 = fmaf(sH1[w][u + 1], sW2[(u + 1) * EMB + e], t1);
    }
    const float h = t0 + t1;

    float ss = h * h;
    ss += __shfl_xor_sync(0xffffffffu, ss, 1);
    ss += __shfl_xor_sync(0xffffffffu, ss, 2);
    ss += __shfl_xor_sync(0xffffffffu, ss, 4);
    ss += __shfl_xor_sync(0xffffffffu, ss, 8);
    const float inv = 1.f / fmaxf(sqrtf(ss), 1e-12f);

    if (lane < EMB) {
        const float alpha = 1.f / (1.f + __expf(-p_raw_alpha[0]));
        const float tau   = fminf(fmaxf(__expf(p_log_tau[0]), 0.1f), 10.f);
        const float kB    = (1.f - alpha) / (tau * 0.6931471805599453f);
        Hout[(size_t)row * EMB + e] = h;
        g_Hn  [row * EMB + e]       = h * inv;
        g_HnTs[e * NPAD + row]      = h * inv * kB;
    }
}

// ======================================================================
// Pass 1 (per row-strip): u' = 2^( dot16 + kA*lg2(A+eps) + 4 ), fp16 -> g_u.
// CTA = 128 threads (natural occ 6 from ~80 regs -> 6 barrier domains/SM).
// Tile 40 rows x 128 cols; thread (tx<16, ty<8): rows ty+8r (r<5),
// cols j0+4tx+64h.  k-loop in chunks of 2 with av via LDS.128.
// ======================================================================
__device__ __forceinline__ void prefetch_tile(float* dst, int j0)
{
    const int tid = threadIdx.x;
    #pragma unroll
    for (int q = 0; q < 4; ++q) {
        const int s  = tid + q * 128;        // 512 float4 slots: 16 k-rows x 32
        const int k  = s >> 5;
        const int cw = s & 31;
        const float* src = g_HnTs + k * NPAD + j0 + 4 * cw;
        unsigned dsts = (unsigned)__cvta_generic_to_shared(dst + k * BN + 4 * cw);
        asm volatile("cp.async.ca.shared.global [%0], [%1], 16;" :: "r"(dsts), "l"(src) : "memory");
    }
    asm volatile("cp.async.commit_group;" ::: "memory");
}

// one 64-col half-tile: 16 tx x 4 contiguous cols each (cols j0 + 4*tx)
__device__ __forceinline__ void tile_u(
    const float* __restrict__ A, int row0,
    const ull* sHnI2, const float* sT,
    int i0, int j0, int ty, int tx,
    float kA, ull bias2, float zacc[5])
{
    // batched A quad-loads (LDG.128, evict-first)
    float4 a4[5];
    #pragma unroll
    for (int r = 0; r < 5; ++r)
        a4[r] = __ldcs((const float4*)(A + (size_t)(i0 + ty + 8 * r) * N_ROWS + j0 + 4 * tx));

    ull acc[5][2];
    #pragma unroll
    for (int r = 0; r < 5; ++r) { acc[r][0] = bias2; acc[r][1] = bias2; }

    #pragma unroll
    for (int k2 = 0; k2 < EMB / 2; ++k2) {                 // chunks of 2 k
        ull2_t av2[5];
        #pragma unroll
        for (int r = 0; r < 5; ++r)                         // LDS.128: k and k+1 pairs
            av2[r] = *(const ull2_t*)(sHnI2 + (ty + 8 * r) * EMB + 2 * k2);
        const ull2_t bv0 = *(const ull2_t*)(sT + (2 * k2    ) * BN + 4 * tx);
        const ull2_t bv1 = *(const ull2_t*)(sT + (2 * k2 + 1) * BN + 4 * tx);
        #pragma unroll
        for (int r = 0; r < 5; ++r) {
            acc[r][0] = ffma2(av2[r].x, bv0.x, acc[r][0]);
            acc[r][1] = ffma2(av2[r].x, bv0.y, acc[r][1]);
            acc[r][0] = ffma2(av2[r].y, bv1.x, acc[r][0]);
            acc[r][1] = ffma2(av2[r].y, bv1.y, acc[r][1]);
        }
    }

    #pragma unroll
    for (int r = 0; r < 5; ++r) {
        const int lrow = i0 - row0 + ty + 8 * r;
        float d0, d1, d2, d3;
        f2up(acc[r][0], d0, d1);
        f2up(acc[r][1], d2, d3);
        float lg0, lg1, lg2v, lg3, u0, u1, u2, u3;
        asm("lg2.approx.f32 %0, %1;" : "=f"(lg0)  : "f"(a4[r].x + 1e-12f));
        asm("lg2.approx.f32 %0, %1;" : "=f"(lg1)  : "f"(a4[r].y + 1e-12f));
        asm("lg2.approx.f32 %0, %1;" : "=f"(lg2v) : "f"(a4[r].z + 1e-12f));
        asm("lg2.approx.f32 %0, %1;" : "=f"(lg3)  : "f"(a4[r].w + 1e-12f));
        const float e0 = fmaf(kA, lg0,  d0);
        const float e1 = fmaf(kA, lg1,  d1);
        const float e2 = fmaf(kA, lg2v, d2);
        const float e3 = fmaf(kA, lg3,  d3);
        asm("ex2.approx.f32 %0, %1;" : "=f"(u0) : "f"(e0));
        asm("ex2.approx.f32 %0, %1;" : "=f"(u1) : "f"(e1));
        asm("ex2.approx.f32 %0, %1;" : "=f"(u2) : "f"(e2));
        asm("ex2.approx.f32 %0, %1;" : "=f"(u3) : "f"(e3));
        const half2 h01 = __floats2half2_rn(u0, u1);
        const half2 h23 = __floats2half2_rn(u2, u3);
        uint2 pk;
        pk.x = *(const unsigned*)&h01;
        pk.y = *(const unsigned*)&h23;
        *(uint2*)(g_u + (size_t)lrow * N_ROWS + j0 + 4 * tx) = pk;    // STG.64
        zacc[r] += (u0 + u1) + (u2 + u3);
    }
}

__global__ void __launch_bounds__(128) upass_kernel(
    const float* __restrict__ A, int row0,
    const float* __restrict__ p_raw_alpha)
{
    __shared__ __align__(16) ull   sHnI2[BM * EMB];      // (v,v) duplicated pairs, 40 rows
    __shared__ __align__(16) float sHnT[2][EMB * BN];

    const int tid   = threadIdx.x;
    const int tx    = tid & 15;
    const int ty    = tid >> 4;                          // [0,8)
    const int strip = blockIdx.x;                        // [0, JSTRIPS)
    const int i0    = row0 + blockIdx.y * BM;

    const float kA    = 1.f / (1.f + __expf(-p_raw_alpha[0]));   // alpha
    const ull   bias2 = f2pk(4.f, 4.f);

    for (int t = tid; t < BM * EMB; t += 128) {
        const float v = g_Hn[i0 * EMB + t];
        sHnI2[t] = f2pk(v, v);
    }

    float zacc[5] = {0.f, 0.f, 0.f, 0.f, 0.f};

    prefetch_tile(&sHnT[0][0], strip * BN);
    int buf = 0;
    for (int jt = strip; jt < NJT; jt += JSTRIPS) {
        const int nxt = jt + JSTRIPS;
        if (nxt < NJT) {
            prefetch_tile(&sHnT[buf ^ 1][0], nxt * BN);
            asm volatile("cp.async.wait_group 1;" ::: "memory");
        } else {
            asm volatile("cp.async.wait_group 0;" ::: "memory");
        }
        __syncthreads();
        const float* sT = &sHnT[buf][0];
        if (jt == NJT - 1) {
            if (tx < 4)    // last tile: 16 real cols = 4 quads
                tile_u(A, row0, sHnI2, sT, i0, jt * BN, ty, tx, kA, bias2, zacc);
        } else {
            #pragma unroll 1
            for (int h = 0; h < 2; ++h)
                tile_u(A, row0, sHnI2, sT + 64 * h, i0, jt * BN + 64 * h,
                       ty, tx, kA, bias2, zacc);
        }
        __syncthreads();
        buf ^= 1;
    }

    #pragma unroll
    for (int r = 0; r < 5; ++r) {
        float z = zacc[r];
        z += __shfl_xor_sync(0xffffffffu, z, 1);
        z += __shfl_xor_sync(0xffffffffu, z, 2);
        z += __shfl_xor_sync(0xffffffffu, z, 4);
        z += __shfl_xor_sync(0xffffffffu, z, 8);
        if (tx == 0) g_Zpart[strip * SROWS + (i0 - row0) + ty + 8 * r] = z;
    }
}

// ======================================================================
// Pass 2 (per strip): W = u' * invZ.  One row per CTA; 5 batched uint4
// loads per thread (MLP), __stcs float4 stores.  invZ computed inline.
// ======================================================================
__global__ void __launch_bounds__(256) scale_kernel(float* __restrict__ Wout, int row0)
{
    const int row = blockIdx.x;                           // local row in strip
    const int tid = threadIdx.x;

    float z = 0.f;
    #pragma unroll
    for (int s = 0; s < JSTRIPS; ++s) z += g_Zpart[s * SROWS + row];
    const float iz = 1.f / z;

    const uint4* up = (const uint4*)(g_u + (size_t)row * N_ROWS);   // 1250 uint4 per row
    float*       wp = Wout + (size_t)(row0 + row) * N_ROWS;

    uint4 raw[5];
    #pragma unroll
    for (int it = 0; it < 5; ++it) {
        const int idx = tid + 256 * it;
        if (idx < 1250) raw[it] = __ldcs(up + idx);
    }
    #pragma unroll
    for (int it = 0; it < 5; ++it) {
        const int idx = tid + 256 * it;
        if (idx < 1250) {
            const float2 f0 = __half22float2(*(const half2*)&raw[it].x);
            const float2 f1 = __half22float2(*(const half2*)&raw[it].y);
            const float2 f2 = __half22float2(*(const half2*)&raw[it].z);
            const float2 f3 = __half22float2(*(const half2*)&raw[it].w);
            __stcs((float4*)(wp + idx * 8),     make_float4(f0.x * iz, f0.y * iz, f1.x * iz, f1.y * iz));
            __stcs((float4*)(wp + idx * 8) + 1, make_float4(f2.x * iz, f2.y * iz, f3.x * iz, f3.y * iz));
        }
    }
}

// ======================================================================
extern "C" void kernel_launch(void* const* d_in, const int* in_sizes, int n_in,
                              void* d_out, int out_size)
{
    (void)in_sizes; (void)n_in; (void)out_size;
    const float* X         = (const float*)d_in[0];
    const float* A         = (const float*)d_in[1];
    const float* W1        = (const float*)d_in[2];
    const float* b1        = (const float*)d_in[3];
    const float* W2        = (const float*)d_in[4];
    const float* b2        = (const float*)d_in[5];
    const float* log_tau   = (const float*)d_in[6];
    const float* raw_alpha = (const float*)d_in[7];

    float* out  = (float*)d_out;
    float* Wout = out;                                   // (N, N) first
    float* Hout = out + (size_t)N_ROWS * N_ROWS;         // (N, EMB) second

    encoder_kernel<<<NPAD / 8, 256>>>(X, W1, b1, W2, b2, Hout, log_tau, raw_alpha);

    for (int s = 0; s < NSTRIP; ++s) {
        const int row0 = s * SROWS;
        upass_kernel<<<dim3(JSTRIPS, SROWS / BM), 128>>>(A, row0, raw_alpha);
        scale_kernel<<<SROWS, 256>>>(Wout, row0);
    }
}

// round 12
// speedup vs baseline: 1.0947x; 1.0947x over previous
#include <cuda_runtime.h>
#include <cuda_fp16.h>
#include <cstdint>

#define N_ROWS   10000
#define NPAD     10112          // padded for HnT tiles (10112 = 79*128)
#define D_IN     128
#define HID      32
#define EMB      16
#define NJT      79             // ceil(10000/128) column tiles
#define BM       80             // rows per CTA tile (25 * 80 = 2000 strip rows)
#define BN       128            // cols per CTA tile
#define SROWS    2000           // rows per L2 strip (5 strips)
#define NSTRIP   5
#define JSTRIPS  16             // 16 * 25 = 400 CTAs/launch <= 592 slots @ occ4

typedef unsigned long long ull;
struct __align__(16) ull2_t { ull x, y; };

// ---------------- static device scratch (no runtime allocations) ----------------
__device__ __align__(16) float g_Hn  [NPAD * EMB];       // normalized embeddings, row-major
__device__ __align__(16) float g_HnTs[EMB * NPAD];       // transposed, pre-scaled by kB
__device__ __align__(16) float g_Zpart[JSTRIPS * SROWS];
__device__ __align__(16) __half g_u[(size_t)SROWS * N_ROWS];  // 40MB fp16 u' strip (L2-resident)

// ---------------- f32x2 helpers ----------------
__device__ __forceinline__ ull f2pk(float lo, float hi) {
    ull r; asm("mov.b64 %0, {%1, %2};" : "=l"(r) : "f"(lo), "f"(hi)); return r;
}
__device__ __forceinline__ void f2up(ull v, float& lo, float& hi) {
    asm("mov.b64 {%0, %1}, %2;" : "=f"(lo), "=f"(hi) : "l"(v));
}
__device__ __forceinline__ ull ffma2(ull a, ull b, ull c) {
    ull d; asm("fma.rn.f32x2 %0, %1, %2, %3;" : "=l"(d) : "l"(a), "l"(b), "l"(c)); return d;
}

// ======================================================================
// Kernel 1: encoder.  H = relu(X@W1 + b1)@W2 + b2 ; Hn = H / max(||H||,1e-12)
// ======================================================================
__global__ void __launch_bounds__(256) encoder_kernel(
    const float* __restrict__ X, const float* __restrict__ W1,
    const float* __restrict__ b1, const float* __restrict__ W2,
    const float* __restrict__ b2, float* __restrict__ Hout,
    const float* __restrict__ p_log_tau, const float* __restrict__ p_raw_alpha)
{
    __shared__ float sW1[D_IN * HID];
    __shared__ float sW2[HID * EMB];
    __shared__ float sb1[HID];
    __shared__ float sb2[EMB];
    __shared__ float sX[8][D_IN];
    __shared__ float sH1[8][HID];

    const int tid = threadIdx.x;
    for (int i = tid; i < D_IN * HID; i += 256) sW1[i] = W1[i];
    for (int i = tid; i < HID * EMB;  i += 256) sW2[i] = W2[i];
    if (tid < HID) sb1[tid] = b1[tid];
    if (tid < EMB) sb2[tid] = b2[tid];
    __syncthreads();

    const int w    = tid >> 5;
    const int lane = tid & 31;
    const int row  = blockIdx.x * 8 + w;
    if (row >= NPAD) return;

    if (row >= N_ROWS) {
        if (lane < EMB) {
            g_Hn  [row * EMB + lane]  = 0.f;
            g_HnTs[lane * NPAD + row] = 0.f;
        }
        return;
    }

    #pragma unroll
    for (int q = 0; q < 4; ++q) sX[w][lane + 32 * q] = X[(size_t)row * D_IN + lane + 32 * q];
    __syncwarp();

    float s0 = sb1[lane], s1 = 0.f, s2 = 0.f, s3 = 0.f;
    #pragma unroll
    for (int k = 0; k < D_IN; k += 4) {
        s0 = fmaf(sX[w][k    ], sW1[(k    ) * HID + lane], s0);
        s1 = fmaf(sX[w][k + 1], sW1[(k + 1) * HID + lane], s1);
        s2 = fmaf(sX[w][k + 2], sW1[(k + 2) * HID + lane], s2);
        s3 = fmaf(sX[w][k + 3], sW1[(k + 3) * HID + lane], s3);
    }
    float h1 = fmaxf((s0 + s1) + (s2 + s3), 0.f);
    sH1[w][lane] = h1;
    __syncwarp();

    const int e = lane & 15;
    float t0 = sb2[e], t1 = 0.f;
    #pragma unroll
    for (int u = 0; u < HID; u += 2) {
        t0 = fmaf(sH1[w][u    ], sW2[(u    ) * EMB + e], t0);
        t1 = fmaf(sH1[w][u + 1], sW2[(u + 1) * EMB + e], t1);
    }
    const float h = t0 + t1;

    float ss = h * h;
    ss += __shfl_xor_sync(0xffffffffu, ss, 1);
    ss += __shfl_xor_sync(0xffffffffu, ss, 2);
    ss += __shfl_xor_sync(0xffffffffu, ss, 4);
    ss += __shfl_xor_sync(0xffffffffu, ss, 8);
    const float inv = 1.f / fmaxf(sqrtf(ss), 1e-12f);

    if (lane < EMB) {
        const float alpha = 1.f / (1.f + __expf(-p_raw_alpha[0]));
        const float tau   = fminf(fmaxf(__expf(p_log_tau[0]), 0.1f), 10.f);
        const float kB    = (1.f - alpha) / (tau * 0.6931471805599453f);
        Hout[(size_t)row * EMB + e] = h;
        g_Hn  [row * EMB + e]       = h * inv;
        g_HnTs[e * NPAD + row]      = h * inv * kB;
    }
}

// ======================================================================
// Pass 1 (per row-strip): u' = 2^( dot16 + kA*lg2(A+eps) + 4 ), fp16 -> g_u.
// R9 geometry: CTA 256 thr, tile 80x128; thread (tx<16, ty<16): rows
// ty+16r (r<5), cols j0+4tx per 64-col half.  occ forced to 4 (32 warps/SM).
// ======================================================================
__device__ __forceinline__ void prefetch_tile(float* dst, int j0)
{
    const int tid = threadIdx.x;
    #pragma unroll
    for (int q = 0; q < 2; ++q) {
        const int s  = tid + q * 256;        // 512 float4 slots: 16 k-rows x 32
        const int k  = s >> 5;
        const int cw = s & 31;
        const float* src = g_HnTs + k * NPAD + j0 + 4 * cw;
        unsigned dsts = (unsigned)__cvta_generic_to_shared(dst + k * BN + 4 * cw);
        asm volatile("cp.async.ca.shared.global [%0], [%1], 16;" :: "r"(dsts), "l"(src) : "memory");
    }
    asm volatile("cp.async.commit_group;" ::: "memory");
}

// one 64-col half-tile: 16 tx x 4 contiguous cols each (cols j0 + 4*tx)
__device__ __forceinline__ void tile_u(
    const float* __restrict__ A, int row0,
    const ull* sHnI2, const float* sT,
    int i0, int j0, int ty, int tx,
    float kA, ull bias2, float zacc[5])
{
    // batched A quad-loads (LDG.128, evict-first)
    float4 a4[5];
    #pragma unroll
    for (int r = 0; r < 5; ++r)
        a4[r] = __ldcs((const float4*)(A + (size_t)(i0 + ty + 16 * r) * N_ROWS + j0 + 4 * tx));

    ull acc[5][2];
    #pragma unroll
    for (int r = 0; r < 5; ++r) { acc[r][0] = bias2; acc[r][1] = bias2; }

    #pragma unroll
    for (int k = 0; k < EMB; ++k) {
        ull av[5];
        #pragma unroll
        for (int r = 0; r < 5; ++r) av[r] = sHnI2[(ty + 16 * r) * EMB + k];
        const ull2_t bv = *(const ull2_t*)(sT + k * BN + 4 * tx);     // LDS.128 = 2 col-pairs
        #pragma unroll
        for (int r = 0; r < 5; ++r) {
            acc[r][0] = ffma2(av[r], bv.x, acc[r][0]);
            acc[r][1] = ffma2(av[r], bv.y, acc[r][1]);
        }
    }

    #pragma unroll
    for (int r = 0; r < 5; ++r) {
        const int lrow = i0 - row0 + ty + 16 * r;
        float d0, d1, d2, d3;
        f2up(acc[r][0], d0, d1);
        f2up(acc[r][1], d2, d3);
        float lg0, lg1, lg2v, lg3, u0, u1, u2, u3;
        asm("lg2.approx.f32 %0, %1;" : "=f"(lg0)  : "f"(a4[r].x + 1e-12f));
        asm("lg2.approx.f32 %0, %1;" : "=f"(lg1)  : "f"(a4[r].y + 1e-12f));
        asm("lg2.approx.f32 %0, %1;" : "=f"(lg2v) : "f"(a4[r].z + 1e-12f));
        asm("lg2.approx.f32 %0, %1;" : "=f"(lg3)  : "f"(a4[r].w + 1e-12f));
        const float e0 = fmaf(kA, lg0,  d0);
        const float e1 = fmaf(kA, lg1,  d1);
        const float e2 = fmaf(kA, lg2v, d2);
        const float e3 = fmaf(kA, lg3,  d3);
        asm("ex2.approx.f32 %0, %1;" : "=f"(u0) : "f"(e0));
        asm("ex2.approx.f32 %0, %1;" : "=f"(u1) : "f"(e1));
        asm("ex2.approx.f32 %0, %1;" : "=f"(u2) : "f"(e2));
        asm("ex2.approx.f32 %0, %1;" : "=f"(u3) : "f"(e3));
        const half2 h01 = __floats2half2_rn(u0, u1);
        const half2 h23 = __floats2half2_rn(u2, u3);
        uint2 pk;
        pk.x = *(const unsigned*)&h01;
        pk.y = *(const unsigned*)&h23;
        *(uint2*)(g_u + (size_t)lrow * N_ROWS + j0 + 4 * tx) = pk;    // STG.64
        zacc[r] += (u0 + u1) + (u2 + u3);
    }
}

__global__ void __launch_bounds__(256, 4) upass_kernel(
    const float* __restrict__ A, int row0,
    const float* __restrict__ p_raw_alpha)
{
    __shared__ __align__(16) ull   sHnI2[BM * EMB];      // (v,v) duplicated pairs
    __shared__ __align__(16) float sHnT[2][EMB * BN];

    const int tid   = threadIdx.x;
    const int tx    = tid & 15;
    const int ty    = tid >> 4;                          // [0,16)
    const int strip = blockIdx.x;                        // [0, JSTRIPS)
    const int i0    = row0 + blockIdx.y * BM;

    const float kA    = 1.f / (1.f + __expf(-p_raw_alpha[0]));   // alpha
    const ull   bias2 = f2pk(4.f, 4.f);

    for (int t = tid; t < BM * EMB; t += 256) {
        const float v = g_Hn[i0 * EMB + t];
        sHnI2[t] = f2pk(v, v);
    }

    float zacc[5] = {0.f, 0.f, 0.f, 0.f, 0.f};

    prefetch_tile(&sHnT[0][0], strip * BN);
    int buf = 0;
    for (int jt = strip; jt < NJT; jt += JSTRIPS) {
        const int nxt = jt + JSTRIPS;
        if (nxt < NJT) {
            prefetch_tile(&sHnT[buf ^ 1][0], nxt * BN);
            asm volatile("cp.async.wait_group 1;" ::: "memory");
        } else {
            asm volatile("cp.async.wait_group 0;" ::: "memory");
        }
        __syncthreads();
        const float* sT = &sHnT[buf][0];
        if (jt == NJT - 1) {
            if (tx < 4)    // last tile: 16 real cols = 4 quads
                tile_u(A, row0, sHnI2, sT, i0, jt * BN, ty, tx, kA, bias2, zacc);
        } else {
            #pragma unroll 1
            for (int h = 0; h < 2; ++h)
                tile_u(A, row0, sHnI2, sT + 64 * h, i0, jt * BN + 64 * h,
                       ty, tx, kA, bias2, zacc);
        }
        __syncthreads();
        buf ^= 1;
    }

    #pragma unroll
    for (int r = 0; r < 5; ++r) {
        float z = zacc[r];
        z += __shfl_xor_sync(0xffffffffu, z, 1);
        z += __shfl_xor_sync(0xffffffffu, z, 2);
        z += __shfl_xor_sync(0xffffffffu, z, 4);
        z += __shfl_xor_sync(0xffffffffu, z, 8);
        if (tx == 0) g_Zpart[strip * SROWS + (i0 - row0) + ty + 16 * r] = z;
    }
}

// ======================================================================
// Pass 2 (per strip): W = u' * invZ.  One row per CTA; 5 batched uint4
// loads per thread (MLP), __stcs float4 stores.  invZ computed inline.
// ======================================================================
__global__ void __launch_bounds__(256) scale_kernel(float* __restrict__ Wout, int row0)
{
    const int row = blockIdx.x;                           // local row in strip
    const int tid = threadIdx.x;

    float z = 0.f;
    #pragma unroll
    for (int s = 0; s < JSTRIPS; ++s) z += g_Zpart[s * SROWS + row];
    const float iz = 1.f / z;

    const uint4* up = (const uint4*)(g_u + (size_t)row * N_ROWS);   // 1250 uint4 per row
    float*       wp = Wout + (size_t)(row0 + row) * N_ROWS;

    uint4 raw[5];
    #pragma unroll
    for (int it = 0; it < 5; ++it) {
        const int idx = tid + 256 * it;
        if (idx < 1250) raw[it] = __ldcs(up + idx);
    }
    #pragma unroll
    for (int it = 0; it < 5; ++it) {
        const int idx = tid + 256 * it;
        if (idx < 1250) {
            const float2 f0 = __half22float2(*(const half2*)&raw[it].x);
            const float2 f1 = __half22float2(*(const half2*)&raw[it].y);
            const float2 f2 = __half22float2(*(const half2*)&raw[it].z);
            const float2 f3 = __half22float2(*(const half2*)&raw[it].w);
            __stcs((float4*)(wp + idx * 8),     make_float4(f0.x * iz, f0.y * iz, f1.x * iz, f1.y * iz));
            __stcs((float4*)(wp + idx * 8) + 1, make_float4(f2.x * iz, f2.y * iz, f3.x * iz, f3.y * iz));
        }
    }
}

// ======================================================================
extern "C" void kernel_launch(void* const* d_in, const int* in_sizes, int n_in,
                              void* d_out, int out_size)
{
    (void)in_sizes; (void)n_in; (void)out_size;
    const float* X         = (const float*)d_in[0];
    const float* A         = (const float*)d_in[1];
    const float* W1        = (const float*)d_in[2];
    const float* b1        = (const float*)d_in[3];
    const float* W2        = (const float*)d_in[4];
    const float* b2        = (const float*)d_in[5];
    const float* log_tau   = (const float*)d_in[6];
    const float* raw_alpha = (const float*)d_in[7];

    float* out  = (float*)d_out;
    float* Wout = out;                                   // (N, N) first
    float* Hout = out + (size_t)N_ROWS * N_ROWS;         // (N, EMB) second

    encoder_kernel<<<NPAD / 8, 256>>>(X, W1, b1, W2, b2, Hout, log_tau, raw_alpha);

    for (int s = 0; s < NSTRIP; ++s) {
        const int row0 = s * SROWS;
        upass_kernel<<<dim3(JSTRIPS, SROWS / BM), 256>>>(A, row0, raw_alpha);
        scale_kernel<<<SROWS, 256>>>(Wout, row0);
    }
}

// round 13
// speedup vs baseline: 1.1328x; 1.0348x over previous
#include <cuda_runtime.h>
#include <cuda_fp16.h>
#include <cstdint>

#define N_ROWS   10000
#define NPAD     10112          // padded for HnT tiles (10112 = 79*128)
#define D_IN     128
#define HID      32
#define EMB      16
#define NJT      79             // ceil(10000/128) column tiles
#define BM       80             // rows per CTA tile (25 * 80 = 2000 strip rows)
#define BN       128            // cols per CTA tile
#define SROWS    2000           // rows per L2 strip (5 strips)
#define NSTRIP   5
#define JSTRIPS  23             // 23 * 25 = 575 CTAs <= 592 slots @ occ4 -> SMs actually get 4 CTAs

typedef unsigned long long ull;
struct __align__(16) ull2_t { ull x, y; };

// ---------------- static device scratch (no runtime allocations) ----------------
__device__ __align__(16) float g_Hn  [NPAD * EMB];       // normalized embeddings, row-major
__device__ __align__(16) float g_HnTs[EMB * NPAD];       // transposed, pre-scaled by kB
__device__ __align__(16) float g_Zpart[JSTRIPS * SROWS];
__device__ __align__(16) __half g_u[(size_t)SROWS * N_ROWS];  // 40MB fp16 u' strip (L2-resident)

// ---------------- f32x2 helpers ----------------
__device__ __forceinline__ ull f2pk(float lo, float hi) {
    ull r; asm("mov.b64 %0, {%1, %2};" : "=l"(r) : "f"(lo), "f"(hi)); return r;
}
__device__ __forceinline__ void f2up(ull v, float& lo, float& hi) {
    asm("mov.b64 {%0, %1}, %2;" : "=f"(lo), "=f"(hi) : "l"(v));
}
__device__ __forceinline__ ull ffma2(ull a, ull b, ull c) {
    ull d; asm("fma.rn.f32x2 %0, %1, %2, %3;" : "=l"(d) : "l"(a), "l"(b), "l"(c)); return d;
}

// ======================================================================
// Kernel 1: encoder.  H = relu(X@W1 + b1)@W2 + b2 ; Hn = H / max(||H||,1e-12)
// ======================================================================
__global__ void __launch_bounds__(256) encoder_kernel(
    const float* __restrict__ X, const float* __restrict__ W1,
    const float* __restrict__ b1, const float* __restrict__ W2,
    const float* __restrict__ b2, float* __restrict__ Hout,
    const float* __restrict__ p_log_tau, const float* __restrict__ p_raw_alpha)
{
    __shared__ float sW1[D_IN * HID];
    __shared__ float sW2[HID * EMB];
    __shared__ float sb1[HID];
    __shared__ float sb2[EMB];
    __shared__ float sX[8][D_IN];
    __shared__ float sH1[8][HID];

    const int tid = threadIdx.x;
    for (int i = tid; i < D_IN * HID; i += 256) sW1[i] = W1[i];
    for (int i = tid; i < HID * EMB;  i += 256) sW2[i] = W2[i];
    if (tid < HID) sb1[tid] = b1[tid];
    if (tid < EMB) sb2[tid] = b2[tid];
    __syncthreads();

    const int w    = tid >> 5;
    const int lane = tid & 31;
    const int row  = blockIdx.x * 8 + w;
    if (row >= NPAD) return;

    if (row >= N_ROWS) {
        if (lane < EMB) {
            g_Hn  [row * EMB + lane]  = 0.f;
            g_HnTs[lane * NPAD + row] = 0.f;
        }
        return;
    }

    #pragma unroll
    for (int q = 0; q < 4; ++q) sX[w][lane + 32 * q] = X[(size_t)row * D_IN + lane + 32 * q];
    __syncwarp();

    float s0 = sb1[lane], s1 = 0.f, s2 = 0.f, s3 = 0.f;
    #pragma unroll
    for (int k = 0; k < D_IN; k += 4) {
        s0 = fmaf(sX[w][k    ], sW1[(k    ) * HID + lane], s0);
        s1 = fmaf(sX[w][k + 1], sW1[(k + 1) * HID + lane], s1);
        s2 = fmaf(sX[w][k + 2], sW1[(k + 2) * HID + lane], s2);
        s3 = fmaf(sX[w][k + 3], sW1[(k + 3) * HID + lane], s3);
    }
    float h1 = fmaxf((s0 + s1) + (s2 + s3), 0.f);
    sH1[w][lane] = h1;
    __syncwarp();

    const int e = lane & 15;
    float t0 = sb2[e], t1 = 0.f;
    #pragma unroll
    for (int u = 0; u < HID; u += 2) {
        t0 = fmaf(sH1[w][u    ], sW2[(u    ) * EMB + e], t0);
        t1 = fmaf(sH1[w][u + 1], sW2[(u + 1) * EMB + e], t1);
    }
    const float h = t0 + t1;

    float ss = h * h;
    ss += __shfl_xor_sync(0xffffffffu, ss, 1);
    ss += __shfl_xor_sync(0xffffffffu, ss, 2);
    ss += __shfl_xor_sync(0xffffffffu, ss, 4);
    ss += __shfl_xor_sync(0xffffffffu, ss, 8);
    const float inv = 1.f / fmaxf(sqrtf(ss), 1e-12f);

    if (lane < EMB) {
        const float alpha = 1.f / (1.f + __expf(-p_raw_alpha[0]));
        const float tau   = fminf(fmaxf(__expf(p_log_tau[0]), 0.1f), 10.f);
        const float kB    = (1.f - alpha) / (tau * 0.6931471805599453f);
        Hout[(size_t)row * EMB + e] = h;
        g_Hn  [row * EMB + e]       = h * inv;
        g_HnTs[e * NPAD + row]      = h * inv * kB;
    }
}

// ======================================================================
// Pass 1 (per row-strip): u' = 2^( dot16 + kA*lg2(A+eps) + 4 ), fp16 -> g_u.
// CTA 256 thr, tile 80x128; thread (tx<16, ty<16): rows ty+16r (r<5),
// cols j0+4tx per 64-col half.  occ 4 (32 warps/SM), grid 575 = one wave.
// ======================================================================
__device__ __forceinline__ void prefetch_tile(float* dst, int j0)
{
    const int tid = threadIdx.x;
    #pragma unroll
    for (int q = 0; q < 2; ++q) {
        const int s  = tid + q * 256;        // 512 float4 slots: 16 k-rows x 32
        const int k  = s >> 5;
        const int cw = s & 31;
        const float* src = g_HnTs + k * NPAD + j0 + 4 * cw;
        unsigned dsts = (unsigned)__cvta_generic_to_shared(dst + k * BN + 4 * cw);
        asm volatile("cp.async.ca.shared.global [%0], [%1], 16;" :: "r"(dsts), "l"(src) : "memory");
    }
    asm volatile("cp.async.commit_group;" ::: "memory");
}

// one 64-col half-tile: 16 tx x 4 contiguous cols each (cols j0 + 4*tx)
__device__ __forceinline__ void tile_u(
    const float* __restrict__ A, int row0,
    const ull* sHnI2, const float* sT,
    int i0, int j0, int ty, int tx,
    float kA, ull bias2, float zacc[5])
{
    // batched A quad-loads (LDG.128, evict-first)
    float4 a4[5];
    #pragma unroll
    for (int r = 0; r < 5; ++r)
        a4[r] = __ldcs((const float4*)(A + (size_t)(i0 + ty + 16 * r) * N_ROWS + j0 + 4 * tx));

    ull acc[5][2];
    #pragma unroll
    for (int r = 0; r < 5; ++r) { acc[r][0] = bias2; acc[r][1] = bias2; }

    #pragma unroll
    for (int k = 0; k < EMB; ++k) {
        ull av[5];
        #pragma unroll
        for (int r = 0; r < 5; ++r) av[r] = sHnI2[(ty + 16 * r) * EMB + k];
        const ull2_t bv = *(const ull2_t*)(sT + k * BN + 4 * tx);     // LDS.128 = 2 col-pairs
        #pragma unroll
        for (int r = 0; r < 5; ++r) {
            acc[r][0] = ffma2(av[r], bv.x, acc[r][0]);
            acc[r][1] = ffma2(av[r], bv.y, acc[r][1]);
        }
    }

    #pragma unroll
    for (int r = 0; r < 5; ++r) {
        const int lrow = i0 - row0 + ty + 16 * r;
        float d0, d1, d2, d3;
        f2up(acc[r][0], d0, d1);
        f2up(acc[r][1], d2, d3);
        float lg0, lg1, lg2v, lg3, u0, u1, u2, u3;
        asm("lg2.approx.f32 %0, %1;" : "=f"(lg0)  : "f"(a4[r].x + 1e-12f));
        asm("lg2.approx.f32 %0, %1;" : "=f"(lg1)  : "f"(a4[r].y + 1e-12f));
        asm("lg2.approx.f32 %0, %1;" : "=f"(lg2v) : "f"(a4[r].z + 1e-12f));
        asm("lg2.approx.f32 %0, %1;" : "=f"(lg3)  : "f"(a4[r].w + 1e-12f));
        const float e0 = fmaf(kA, lg0,  d0);
        const float e1 = fmaf(kA, lg1,  d1);
        const float e2 = fmaf(kA, lg2v, d2);
        const float e3 = fmaf(kA, lg3,  d3);
        asm("ex2.approx.f32 %0, %1;" : "=f"(u0) : "f"(e0));
        asm("ex2.approx.f32 %0, %1;" : "=f"(u1) : "f"(e1));
        asm("ex2.approx.f32 %0, %1;" : "=f"(u2) : "f"(e2));
        asm("ex2.approx.f32 %0, %1;" : "=f"(u3) : "f"(e3));
        const half2 h01 = __floats2half2_rn(u0, u1);
        const half2 h23 = __floats2half2_rn(u2, u3);
        uint2 pk;
        pk.x = *(const unsigned*)&h01;
        pk.y = *(const unsigned*)&h23;
        *(uint2*)(g_u + (size_t)lrow * N_ROWS + j0 + 4 * tx) = pk;    // STG.64
        zacc[r] += (u0 + u1) + (u2 + u3);
    }
}

__global__ void __launch_bounds__(256, 4) upass_kernel(
    const float* __restrict__ A, int row0,
    const float* __restrict__ p_raw_alpha)
{
    __shared__ __align__(16) ull   sHnI2[BM * EMB];      // (v,v) duplicated pairs
    __shared__ __align__(16) float sHnT[2][EMB * BN];

    const int tid   = threadIdx.x;
    const int tx    = tid & 15;
    const int ty    = tid >> 4;                          // [0,16)
    const int strip = blockIdx.x;                        // [0, JSTRIPS)
    const int i0    = row0 + blockIdx.y * BM;

    const float kA    = 1.f / (1.f + __expf(-p_raw_alpha[0]));   // alpha
    const ull   bias2 = f2pk(4.f, 4.f);

    for (int t = tid; t < BM * EMB; t += 256) {
        const float v = g_Hn[i0 * EMB + t];
        sHnI2[t] = f2pk(v, v);
    }

    float zacc[5] = {0.f, 0.f, 0.f, 0.f, 0.f};

    prefetch_tile(&sHnT[0][0], strip * BN);
    int buf = 0;
    for (int jt = strip; jt < NJT; jt += JSTRIPS) {
        const int nxt = jt + JSTRIPS;
        if (nxt < NJT) {
            prefetch_tile(&sHnT[buf ^ 1][0], nxt * BN);
            asm volatile("cp.async.wait_group 1;" ::: "memory");
        } else {
            asm volatile("cp.async.wait_group 0;" ::: "memory");
        }
        __syncthreads();
        const float* sT = &sHnT[buf][0];
        if (jt == NJT - 1) {
            if (tx < 4)    // last tile: 16 real cols = 4 quads
                tile_u(A, row0, sHnI2, sT, i0, jt * BN, ty, tx, kA, bias2, zacc);
        } else {
            #pragma unroll 1
            for (int h = 0; h < 2; ++h)
                tile_u(A, row0, sHnI2, sT + 64 * h, i0, jt * BN + 64 * h,
                       ty, tx, kA, bias2, zacc);
        }
        __syncthreads();
        buf ^= 1;
    }

    #pragma unroll
    for (int r = 0; r < 5; ++r) {
        float z = zacc[r];
        z += __shfl_xor_sync(0xffffffffu, z, 1);
        z += __shfl_xor_sync(0xffffffffu, z, 2);
        z += __shfl_xor_sync(0xffffffffu, z, 4);
        z += __shfl_xor_sync(0xffffffffu, z, 8);
        if (tx == 0) g_Zpart[strip * SROWS + (i0 - row0) + ty + 16 * r] = z;
    }
}

// ======================================================================
// Pass 2 (per strip): W = u' * invZ.  One row per CTA; 5 batched uint4
// loads per thread (MLP), __stcs float4 stores.  invZ computed inline.
// ======================================================================
__global__ void __launch_bounds__(256) scale_kernel(float* __restrict__ Wout, int row0)
{
    const int row = blockIdx.x;                           // local row in strip
    const int tid = threadIdx.x;

    float z = 0.f;
    #pragma unroll
    for (int s = 0; s < JSTRIPS; ++s) z += g_Zpart[s * SROWS + row];
    const float iz = 1.f / z;

    const uint4* up = (const uint4*)(g_u + (size_t)row * N_ROWS);   // 1250 uint4 per row
    float*       wp = Wout + (size_t)(row0 + row) * N_ROWS;

    uint4 raw[5];
    #pragma unroll
    for (int it = 0; it < 5; ++it) {
        const int idx = tid + 256 * it;
        if (idx < 1250) raw[it] = __ldcs(up + idx);
    }
    #pragma unroll
    for (int it = 0; it < 5; ++it) {
        const int idx = tid + 256 * it;
        if (idx < 1250) {
            const float2 f0 = __half22float2(*(const half2*)&raw[it].x);
            const float2 f1 = __half22float2(*(const half2*)&raw[it].y);
            const float2 f2 = __half22float2(*(const half2*)&raw[it].z);
            const float2 f3 = __half22float2(*(const half2*)&raw[it].w);
            __stcs((float4*)(wp + idx * 8),     make_float4(f0.x * iz, f0.y * iz, f1.x * iz, f1.y * iz));
            __stcs((float4*)(wp + idx * 8) + 1, make_float4(f2.x * iz, f2.y * iz, f3.x * iz, f3.y * iz));
        }
    }
}

// ======================================================================
extern "C" void kernel_launch(void* const* d_in, const int* in_sizes, int n_in,
                              void* d_out, int out_size)
{
    (void)in_sizes; (void)n_in; (void)out_size;
    const float* X         = (const float*)d_in[0];
    const float* A         = (const float*)d_in[1];
    const float* W1        = (const float*)d_in[2];
    const float* b1        = (const float*)d_in[3];
    const float* W2        = (const float*)d_in[4];
    const float* b2        = (const float*)d_in[5];
    const float* log_tau   = (const float*)d_in[6];
    const float* raw_alpha = (const float*)d_in[7];

    float* out  = (float*)d_out;
    float* Wout = out;                                   // (N, N) first
    float* Hout = out + (size_t)N_ROWS * N_ROWS;         // (N, EMB) second

    encoder_kernel<<<NPAD / 8, 256>>>(X, W1, b1, W2, b2, Hout, log_tau, raw_alpha);

    for (int s = 0; s < NSTRIP; ++s) {
        const int row0 = s * SROWS;
        upass_kernel<<<dim3(JSTRIPS, SROWS / BM), 256>>>(A, row0, raw_alpha);
        scale_kernel<<<SROWS, 256>>>(Wout, row0);
    }
}

// round 14
// speedup vs baseline: 1.1330x; 1.0001x over previous
#include <cuda_runtime.h>
#include <cuda_fp16.h>
#include <cstdint>

#define N_ROWS   10000
#define NPAD     10112          // padded for HnT tiles (10112 = 79*128)
#define D_IN     128
#define HID      32
#define EMB      16
#define NJT      79             // ceil(10000/128) column tiles
#define BM       80             // rows per CTA tile (25 * 80 = 2000 strip rows)
#define BN       128            // cols per CTA tile
#define SROWS    2000           // rows per L2 strip (5 strips)
#define NSTRIP   5
#define JSTRIPS  17             // 17 * 25 = 425 CTAs <= 444 slots @ occ3 -> single wave

typedef unsigned long long ull;
struct __align__(16) ull2_t { ull x, y; };

// ---------------- static device scratch (no runtime allocations) ----------------
__device__ __align__(16) float g_Hn  [NPAD * EMB];       // normalized embeddings, row-major
__device__ __align__(16) float g_HnTs[EMB * NPAD];       // transposed, pre-scaled by kB
__device__ __align__(16) float g_Zpart[JSTRIPS * SROWS];
__device__ __align__(16) __half g_u[(size_t)SROWS * N_ROWS];  // 40MB fp16 u' strip (L2-resident)

// ---------------- f32x2 helpers ----------------
__device__ __forceinline__ ull f2pk(float lo, float hi) {
    ull r; asm("mov.b64 %0, {%1, %2};" : "=l"(r) : "f"(lo), "f"(hi)); return r;
}
__device__ __forceinline__ void f2up(ull v, float& lo, float& hi) {
    asm("mov.b64 {%0, %1}, %2;" : "=f"(lo), "=f"(hi) : "l"(v));
}
__device__ __forceinline__ ull ffma2(ull a, ull b, ull c) {
    ull d; asm("fma.rn.f32x2 %0, %1, %2, %3;" : "=l"(d) : "l"(a), "l"(b), "l"(c)); return d;
}

// ======================================================================
// Kernel 1: encoder.  H = relu(X@W1 + b1)@W2 + b2 ; Hn = H / max(||H||,1e-12)
// ======================================================================
__global__ void __launch_bounds__(256) encoder_kernel(
    const float* __restrict__ X, const float* __restrict__ W1,
    const float* __restrict__ b1, const float* __restrict__ W2,
    const float* __restrict__ b2, float* __restrict__ Hout,
    const float* __restrict__ p_log_tau, const float* __restrict__ p_raw_alpha)
{
    __shared__ float sW1[D_IN * HID];
    __shared__ float sW2[HID * EMB];
    __shared__ float sb1[HID];
    __shared__ float sb2[EMB];
    __shared__ float sX[8][D_IN];
    __shared__ float sH1[8][HID];

    const int tid = threadIdx.x;
    for (int i = tid; i < D_IN * HID; i += 256) sW1[i] = W1[i];
    for (int i = tid; i < HID * EMB;  i += 256) sW2[i] = W2[i];
    if (tid < HID) sb1[tid] = b1[tid];
    if (tid < EMB) sb2[tid] = b2[tid];
    __syncthreads();

    const int w    = tid >> 5;
    const int lane = tid & 31;
    const int row  = blockIdx.x * 8 + w;
    if (row >= NPAD) return;

    if (row >= N_ROWS) {
        if (lane < EMB) {
            g_Hn  [row * EMB + lane]  = 0.f;
            g_HnTs[lane * NPAD + row] = 0.f;
        }
        return;
    }

    #pragma unroll
    for (int q = 0; q < 4; ++q) sX[w][lane + 32 * q] = X[(size_t)row * D_IN + lane + 32 * q];
    __syncwarp();

    float s0 = sb1[lane], s1 = 0.f, s2 = 0.f, s3 = 0.f;
    #pragma unroll
    for (int k = 0; k < D_IN; k += 4) {
        s0 = fmaf(sX[w][k    ], sW1[(k    ) * HID + lane], s0);
        s1 = fmaf(sX[w][k + 1], sW1[(k + 1) * HID + lane], s1);
        s2 = fmaf(sX[w][k + 2], sW1[(k + 2) * HID + lane], s2);
        s3 = fmaf(sX[w][k + 3], sW1[(k + 3) * HID + lane], s3);
    }
    float h1 = fmaxf((s0 + s1) + (s2 + s3), 0.f);
    sH1[w][lane] = h1;
    __syncwarp();

    const int e = lane & 15;
    float t0 = sb2[e], t1 = 0.f;
    #pragma unroll
    for (int u = 0; u < HID; u += 2) {
        t0 = fmaf(sH1[w][u    ], sW2[(u    ) * EMB + e], t0);
        t1 = fmaf(sH1[w][u + 1], sW2[(u + 1) * EMB + e], t1);
    }
    const float h = t0 + t1;

    float ss = h * h;
    ss += __shfl_xor_sync(0xffffffffu, ss, 1);
    ss += __shfl_xor_sync(0xffffffffu, ss, 2);
    ss += __shfl_xor_sync(0xffffffffu, ss, 4);
    ss += __shfl_xor_sync(0xffffffffu, ss, 8);
    const float inv = 1.f / fmaxf(sqrtf(ss), 1e-12f);

    if (lane < EMB) {
        const float alpha = 1.f / (1.f + __expf(-p_raw_alpha[0]));
        const float tau   = fminf(fmaxf(__expf(p_log_tau[0]), 0.1f), 10.f);
        const float kB    = (1.f - alpha) / (tau * 0.6931471805599453f);
        Hout[(size_t)row * EMB + e] = h;
        g_Hn  [row * EMB + e]       = h * inv;
        g_HnTs[e * NPAD + row]      = h * inv * kB;
    }
}

// ======================================================================
// Pass 1 (per row-strip): u' = 2^( dot16 + kA*lg2(A+eps) + 4 ), fp16 -> g_u.
// CTA 256 thr, tile 80x128; thread (tx<16, ty<16): rows ty+16r (r<5),
// cols j0+4tx per 64-col half.  k-loop in chunks of 2: av via LDS.128
// of duplicated (v,v) ull pairs -> 7 LDS per 2k instead of 12.
// ======================================================================
__device__ __forceinline__ void prefetch_tile(float* dst, int j0)
{
    const int tid = threadIdx.x;
    #pragma unroll
    for (int q = 0; q < 2; ++q) {
        const int s  = tid + q * 256;        // 512 float4 slots: 16 k-rows x 32
        const int k  = s >> 5;
        const int cw = s & 31;
        const float* src = g_HnTs + k * NPAD + j0 + 4 * cw;
        unsigned dsts = (unsigned)__cvta_generic_to_shared(dst + k * BN + 4 * cw);
        asm volatile("cp.async.ca.shared.global [%0], [%1], 16;" :: "r"(dsts), "l"(src) : "memory");
    }
    asm volatile("cp.async.commit_group;" ::: "memory");
}

// one 64-col half-tile: 16 tx x 4 contiguous cols each (cols j0 + 4*tx)
__device__ __forceinline__ void tile_u(
    const float* __restrict__ A, int row0,
    const ull* sHnI2, const float* sT,
    int i0, int j0, int ty, int tx,
    float kA, ull bias2, float zacc[5])
{
    // batched A quad-loads (LDG.128, evict-first)
    float4 a4[5];
    #pragma unroll
    for (int r = 0; r < 5; ++r)
        a4[r] = __ldcs((const float4*)(A + (size_t)(i0 + ty + 16 * r) * N_ROWS + j0 + 4 * tx));

    ull acc[5][2];
    #pragma unroll
    for (int r = 0; r < 5; ++r) { acc[r][0] = bias2; acc[r][1] = bias2; }

    #pragma unroll
    for (int k2 = 0; k2 < EMB / 2; ++k2) {                 // chunks of 2 k
        ull2_t av2[5];
        #pragma unroll
        for (int r = 0; r < 5; ++r)                         // LDS.128: (v,v) pairs for k, k+1
            av2[r] = *(const ull2_t*)(sHnI2 + (ty + 16 * r) * EMB + 2 * k2);
        const ull2_t bv0 = *(const ull2_t*)(sT + (2 * k2    ) * BN + 4 * tx);
        const ull2_t bv1 = *(const ull2_t*)(sT + (2 * k2 + 1) * BN + 4 * tx);
        #pragma unroll
        for (int r = 0; r < 5; ++r) {
            acc[r][0] = ffma2(av2[r].x, bv0.x, acc[r][0]);
            acc[r][1] = ffma2(av2[r].x, bv0.y, acc[r][1]);
            acc[r][0] = ffma2(av2[r].y, bv1.x, acc[r][0]);
            acc[r][1] = ffma2(av2[r].y, bv1.y, acc[r][1]);
        }
    }

    #pragma unroll
    for (int r = 0; r < 5; ++r) {
        const int lrow = i0 - row0 + ty + 16 * r;
        float d0, d1, d2, d3;
        f2up(acc[r][0], d0, d1);
        f2up(acc[r][1], d2, d3);
        float lg0, lg1, lg2v, lg3, u0, u1, u2, u3;
        asm("lg2.approx.f32 %0, %1;" : "=f"(lg0)  : "f"(a4[r].x + 1e-12f));
        asm("lg2.approx.f32 %0, %1;" : "=f"(lg1)  : "f"(a4[r].y + 1e-12f));
        asm("lg2.approx.f32 %0, %1;" : "=f"(lg2v) : "f"(a4[r].z + 1e-12f));
        asm("lg2.approx.f32 %0, %1;" : "=f"(lg3)  : "f"(a4[r].w + 1e-12f));
        const float e0 = fmaf(kA, lg0,  d0);
        const float e1 = fmaf(kA, lg1,  d1);
        const float e2 = fmaf(kA, lg2v, d2);
        const float e3 = fmaf(kA, lg3,  d3);
        asm("ex2.approx.f32 %0, %1;" : "=f"(u0) : "f"(e0));
        asm("ex2.approx.f32 %0, %1;" : "=f"(u1) : "f"(e1));
        asm("ex2.approx.f32 %0, %1;" : "=f"(u2) : "f"(e2));
        asm("ex2.approx.f32 %0, %1;" : "=f"(u3) : "f"(e3));
        const half2 h01 = __floats2half2_rn(u0, u1);
        const half2 h23 = __floats2half2_rn(u2, u3);
        uint2 pk;
        pk.x = *(const unsigned*)&h01;
        pk.y = *(const unsigned*)&h23;
        *(uint2*)(g_u + (size_t)lrow * N_ROWS + j0 + 4 * tx) = pk;    // STG.64
        zacc[r] += (u0 + u1) + (u2 + u3);
    }
}

__global__ void __launch_bounds__(256, 3) upass_kernel(
    const float* __restrict__ A, int row0,
    const float* __restrict__ p_raw_alpha)
{
    __shared__ __align__(16) ull   sHnI2[BM * EMB];      // (v,v) duplicated pairs
    __shared__ __align__(16) float sHnT[2][EMB * BN];

    const int tid   = threadIdx.x;
    const int tx    = tid & 15;
    const int ty    = tid >> 4;                          // [0,16)
    const int strip = blockIdx.x;                        // [0, JSTRIPS)
    const int i0    = row0 + blockIdx.y * BM;

    const float kA    = 1.f / (1.f + __expf(-p_raw_alpha[0]));   // alpha
    const ull   bias2 = f2pk(4.f, 4.f);

    for (int t = tid; t < BM * EMB; t += 256) {
        const float v = g_Hn[i0 * EMB + t];
        sHnI2[t] = f2pk(v, v);
    }

    float zacc[5] = {0.f, 0.f, 0.f, 0.f, 0.f};

    prefetch_tile(&sHnT[0][0], strip * BN);
    int buf = 0;
    for (int jt = strip; jt < NJT; jt += JSTRIPS) {
        const int nxt = jt + JSTRIPS;
        if (nxt < NJT) {
            prefetch_tile(&sHnT[buf ^ 1][0], nxt * BN);
            asm volatile("cp.async.wait_group 1;" ::: "memory");
        } else {
            asm volatile("cp.async.wait_group 0;" ::: "memory");
        }
        __syncthreads();
        const float* sT = &sHnT[buf][0];
        if (jt == NJT - 1) {
            if (tx < 4)    // last tile: 16 real cols = 4 quads
                tile_u(A, row0, sHnI2, sT, i0, jt * BN, ty, tx, kA, bias2, zacc);
        } else {
            #pragma unroll 1
            for (int h = 0; h < 2; ++h)
                tile_u(A, row0, sHnI2, sT + 64 * h, i0, jt * BN + 64 * h,
                       ty, tx, kA, bias2, zacc);
        }
        __syncthreads();
        buf ^= 1;
    }

    #pragma unroll
    for (int r = 0; r < 5; ++r) {
        float z = zacc[r];
        z += __shfl_xor_sync(0xffffffffu, z, 1);
        z += __shfl_xor_sync(0xffffffffu, z, 2);
        z += __shfl_xor_sync(0xffffffffu, z, 4);
        z += __shfl_xor_sync(0xffffffffu, z, 8);
        if (tx == 0) g_Zpart[strip * SROWS + (i0 - row0) + ty + 16 * r] = z;
    }
}

// ======================================================================
// Pass 2 (per strip): W = u' * invZ.  One row per CTA; 5 batched uint4
// loads per thread (MLP), __stcs float4 stores.  invZ computed inline.
// ======================================================================
__global__ void __launch_bounds__(256) scale_kernel(float* __restrict__ Wout, int row0)
{
    const int row = blockIdx.x;                           // local row in strip
    const int tid = threadIdx.x;

    float z = 0.f;
    #pragma unroll
    for (int s = 0; s < JSTRIPS; ++s) z += g_Zpart[s * SROWS + row];
    const float iz = 1.f / z;

    const uint4* up = (const uint4*)(g_u + (size_t)row * N_ROWS);   // 1250 uint4 per row
    float*       wp = Wout + (size_t)(row0 + row) * N_ROWS;

    uint4 raw[5];
    #pragma unroll
    for (int it = 0; it < 5; ++it) {
        const int idx = tid + 256 * it;
        if (idx < 1250) raw[it] = __ldcs(up + idx);
    }
    #pragma unroll
    for (int it = 0; it < 5; ++it) {
        const int idx = tid + 256 * it;
        if (idx < 1250) {
            const float2 f0 = __half22float2(*(const half2*)&raw[it].x);
            const float2 f1 = __half22float2(*(const half2*)&raw[it].y);
            const float2 f2 = __half22float2(*(const half2*)&raw[it].z);
            const float2 f3 = __half22float2(*(const half2*)&raw[it].w);
            __stcs((float4*)(wp + idx * 8),     make_float4(f0.x * iz, f0.y * iz, f1.x * iz, f1.y * iz));
            __stcs((float4*)(wp + idx * 8) + 1, make_float4(f2.x * iz, f2.y * iz, f3.x * iz, f3.y * iz));
        }
    }
}

// ======================================================================
extern "C" void kernel_launch(void* const* d_in, const int* in_sizes, int n_in,
                              void* d_out, int out_size)
{
    (void)in_sizes; (void)n_in; (void)out_size;
    const float* X         = (const float*)d_in[0];
    const float* A         = (const float*)d_in[1];
    const float* W1        = (const float*)d_in[2];
    const float* b1        = (const float*)d_in[3];
    const float* W2        = (const float*)d_in[4];
    const float* b2        = (const float*)d_in[5];
    const float* log_tau   = (const float*)d_in[6];
    const float* raw_alpha = (const float*)d_in[7];

    float* out  = (float*)d_out;
    float* Wout = out;                                   // (N, N) first
    float* Hout = out + (size_t)N_ROWS * N_ROWS;         // (N, EMB) second

    encoder_kernel<<<NPAD / 8, 256>>>(X, W1, b1, W2, b2, Hout, log_tau, raw_alpha);

    for (int s = 0; s < NSTRIP; ++s) {
        const int row0 = s * SROWS;
        upass_kernel<<<dim3(JSTRIPS, SROWS / BM), 256>>>(A, row0, raw_alpha);
        scale_kernel<<<SROWS, 256>>>(Wout, row0);
    }
}

// round 15
// speedup vs baseline: 1.2602x; 1.1123x over previous
#include <cuda_runtime.h>
#include <cuda_fp16.h>
#include <cstdint>

#define N_ROWS   10000
#define NPAD     10112          // padded for HnT tiles (10112 = 79*128)
#define D_IN     128
#define HID      32
#define EMB      16
#define NJT      79             // ceil(10000/128) column tiles
#define BM       80             // rows per CTA tile (25 * 80 = 2000 strip rows)
#define BN       128            // cols per CTA tile
#define SROWS    2000           // rows per L2 strip (5 strips)
#define NSTRIP   5
#define JSTRIPS  17             // 17 * 25 = 425 upass CTAs (single wave @ occ<=4)
#define UCTAS    (JSTRIPS * (SROWS / BM))   // 425
#define TCTAS    (UCTAS + SROWS)            // 425 upass + 2000 scale = 2425

typedef unsigned long long ull;
struct __align__(16) ull2_t { ull x, y; };

// ---------------- static device scratch (no runtime allocations) ----------------
__device__ __align__(16) float g_Hn  [NPAD * EMB];       // normalized embeddings, row-major
__device__ __align__(16) float g_HnTs[EMB * NPAD];       // transposed, pre-scaled by kB
__device__ __align__(16) float g_Zpart[2][JSTRIPS * SROWS];          // double-buffered
__device__ __align__(16) __half g_u[2][(size_t)SROWS * N_ROWS];      // 2 x 40MB fp16 u' strips

// ---------------- f32x2 helpers ----------------
__device__ __forceinline__ ull f2pk(float lo, float hi) {
    ull r; asm("mov.b64 %0, {%1, %2};" : "=l"(r) : "f"(lo), "f"(hi)); return r;
}
__device__ __forceinline__ void f2up(ull v, float& lo, float& hi) {
    asm("mov.b64 {%0, %1}, %2;" : "=f"(lo), "=f"(hi) : "l"(v));
}
__device__ __forceinline__ ull ffma2(ull a, ull b, ull c) {
    ull d; asm("fma.rn.f32x2 %0, %1, %2, %3;" : "=l"(d) : "l"(a), "l"(b), "l"(c)); return d;
}

// ======================================================================
// Kernel 1: encoder.  H = relu(X@W1 + b1)@W2 + b2 ; Hn = H / max(||H||,1e-12)
// ======================================================================
__global__ void __launch_bounds__(256) encoder_kernel(
    const float* __restrict__ X, const float* __restrict__ W1,
    const float* __restrict__ b1, const float* __restrict__ W2,
    const float* __restrict__ b2, float* __restrict__ Hout,
    const float* __restrict__ p_log_tau, const float* __restrict__ p_raw_alpha)
{
    __shared__ float sW1[D_IN * HID];
    __shared__ float sW2[HID * EMB];
    __shared__ float sb1[HID];
    __shared__ float sb2[EMB];
    __shared__ float sX[8][D_IN];
    __shared__ float sH1[8][HID];

    const int tid = threadIdx.x;
    for (int i = tid; i < D_IN * HID; i += 256) sW1[i] = W1[i];
    for (int i = tid; i < HID * EMB;  i += 256) sW2[i] = W2[i];
    if (tid < HID) sb1[tid] = b1[tid];
    if (tid < EMB) sb2[tid] = b2[tid];
    __syncthreads();

    const int w    = tid >> 5;
    const int lane = tid & 31;
    const int row  = blockIdx.x * 8 + w;
    if (row >= NPAD) return;

    if (row >= N_ROWS) {
        if (lane < EMB) {
            g_Hn  [row * EMB + lane]  = 0.f;
            g_HnTs[lane * NPAD + row] = 0.f;
        }
        return;
    }

    #pragma unroll
    for (int q = 0; q < 4; ++q) sX[w][lane + 32 * q] = X[(size_t)row * D_IN + lane + 32 * q];
    __syncwarp();

    float s0 = sb1[lane], s1 = 0.f, s2 = 0.f, s3 = 0.f;
    #pragma unroll
    for (int k = 0; k < D_IN; k += 4) {
        s0 = fmaf(sX[w][k    ], sW1[(k    ) * HID + lane], s0);
        s1 = fmaf(sX[w][k + 1], sW1[(k + 1) * HID + lane], s1);
        s2 = fmaf(sX[w][k + 2], sW1[(k + 2) * HID + lane], s2);
        s3 = fmaf(sX[w][k + 3], sW1[(k + 3) * HID + lane], s3);
    }
    float h1 = fmaxf((s0 + s1) + (s2 + s3), 0.f);
    sH1[w][lane] = h1;
    __syncwarp();

    const int e = lane & 15;
    float t0 = sb2[e], t1 = 0.f;
    #pragma unroll
    for (int u = 0; u < HID; u += 2) {
        t0 = fmaf(sH1[w][u    ], sW2[(u    ) * EMB + e], t0);
        t1 = fmaf(sH1[w][u + 1], sW2[(u + 1) * EMB + e], t1);
    }
    const float h = t0 + t1;

    float ss = h * h;
    ss += __shfl_xor_sync(0xffffffffu, ss, 1);
    ss += __shfl_xor_sync(0xffffffffu, ss, 2);
    ss += __shfl_xor_sync(0xffffffffu, ss, 4);
    ss += __shfl_xor_sync(0xffffffffu, ss, 8);
    const float inv = 1.f / fmaxf(sqrtf(ss), 1e-12f);

    if (lane < EMB) {
        const float alpha = 1.f / (1.f + __expf(-p_raw_alpha[0]));
        const float tau   = fminf(fmaxf(__expf(p_log_tau[0]), 0.1f), 10.f);
        const float kB    = (1.f - alpha) / (tau * 0.6931471805599453f);
        Hout[(size_t)row * EMB + e] = h;
        g_Hn  [row * EMB + e]       = h * inv;
        g_HnTs[e * NPAD + row]      = h * inv * kB;
    }
}

// ======================================================================
// upass tile machinery (R12 body: per-k av LDS.64, bv LDS.128; 64 regs)
// ======================================================================
__device__ __forceinline__ void prefetch_tile(float* dst, int j0)
{
    const int tid = threadIdx.x;
    #pragma unroll
    for (int q = 0; q < 2; ++q) {
        const int s  = tid + q * 256;        // 512 float4 slots: 16 k-rows x 32
        const int k  = s >> 5;
        const int cw = s & 31;
        const float* src = g_HnTs + k * NPAD + j0 + 4 * cw;
        unsigned dsts = (unsigned)__cvta_generic_to_shared(dst + k * BN + 4 * cw);
        asm volatile("cp.async.ca.shared.global [%0], [%1], 16;" :: "r"(dsts), "l"(src) : "memory");
    }
    asm volatile("cp.async.commit_group;" ::: "memory");
}

// one 64-col half-tile: 16 tx x 4 contiguous cols each (cols j0 + 4*tx)
__device__ __forceinline__ void tile_u(
    const float* __restrict__ A, int row0, __half* __restrict__ ubuf,
    const ull* sHnI2, const float* sT,
    int i0, int j0, int ty, int tx,
    float kA, ull bias2, float zacc[5])
{
    // batched A quad-loads (LDG.128, evict-first)
    float4 a4[5];
    #pragma unroll
    for (int r = 0; r < 5; ++r)
        a4[r] = __ldcs((const float4*)(A + (size_t)(i0 + ty + 16 * r) * N_ROWS + j0 + 4 * tx));

    ull acc[5][2];
    #pragma unroll
    for (int r = 0; r < 5; ++r) { acc[r][0] = bias2; acc[r][1] = bias2; }

    #pragma unroll
    for (int k = 0; k < EMB; ++k) {
        ull av[5];
        #pragma unroll
        for (int r = 0; r < 5; ++r) av[r] = sHnI2[(ty + 16 * r) * EMB + k];
        const ull2_t bv = *(const ull2_t*)(sT + k * BN + 4 * tx);     // LDS.128 = 2 col-pairs
        #pragma unroll
        for (int r = 0; r < 5; ++r) {
            acc[r][0] = ffma2(av[r], bv.x, acc[r][0]);
            acc[r][1] = ffma2(av[r], bv.y, acc[r][1]);
        }
    }

    #pragma unroll
    for (int r = 0; r < 5; ++r) {
        const int lrow = i0 - row0 + ty + 16 * r;
        float d0, d1, d2, d3;
        f2up(acc[r][0], d0, d1);
        f2up(acc[r][1], d2, d3);
        float lg0, lg1, lg2v, lg3, u0, u1, u2, u3;
        asm("lg2.approx.f32 %0, %1;" : "=f"(lg0)  : "f"(a4[r].x + 1e-12f));
        asm("lg2.approx.f32 %0, %1;" : "=f"(lg1)  : "f"(a4[r].y + 1e-12f));
        asm("lg2.approx.f32 %0, %1;" : "=f"(lg2v) : "f"(a4[r].z + 1e-12f));
        asm("lg2.approx.f32 %0, %1;" : "=f"(lg3)  : "f"(a4[r].w + 1e-12f));
        const float e0 = fmaf(kA, lg0,  d0);
        const float e1 = fmaf(kA, lg1,  d1);
        const float e2 = fmaf(kA, lg2v, d2);
        const float e3 = fmaf(kA, lg3,  d3);
        asm("ex2.approx.f32 %0, %1;" : "=f"(u0) : "f"(e0));
        asm("ex2.approx.f32 %0, %1;" : "=f"(u1) : "f"(e1));
        asm("ex2.approx.f32 %0, %1;" : "=f"(u2) : "f"(e2));
        asm("ex2.approx.f32 %0, %1;" : "=f"(u3) : "f"(e3));
        const half2 h01 = __floats2half2_rn(u0, u1);
        const half2 h23 = __floats2half2_rn(u2, u3);
        uint2 pk;
        pk.x = *(const unsigned*)&h01;
        pk.y = *(const unsigned*)&h23;
        *(uint2*)(ubuf + (size_t)lrow * N_ROWS + j0 + 4 * tx) = pk;   // STG.64
        zacc[r] += (u0 + u1) + (u2 + u3);
    }
}

// scale one row (256 threads): W[grow] = u'[lrow] * invZ
__device__ __forceinline__ void scale_row(
    float* __restrict__ Wout, const __half* __restrict__ ubuf,
    const float* __restrict__ zbuf, int row0p, int lrow)
{
    const int tid = threadIdx.x;
    float z = 0.f;
    #pragma unroll
    for (int s = 0; s < JSTRIPS; ++s) z += zbuf[s * SROWS + lrow];
    const float iz = 1.f / z;

    const uint4* up = (const uint4*)(ubuf + (size_t)lrow * N_ROWS);   // 1250 uint4 per row
    float*       wp = Wout + (size_t)(row0p + lrow) * N_ROWS;

    uint4 raw[5];
    #pragma unroll
    for (int it = 0; it < 5; ++it) {
        const int idx = tid + 256 * it;
        if (idx < 1250) raw[it] = __ldcs(up + idx);
    }
    #pragma unroll
    for (int it = 0; it < 5; ++it) {
        const int idx = tid + 256 * it;
        if (idx < 1250) {
            const float2 f0 = __half22float2(*(const half2*)&raw[it].x);
            const float2 f1 = __half22float2(*(const half2*)&raw[it].y);
            const float2 f2 = __half22float2(*(const half2*)&raw[it].z);
            const float2 f3 = __half22float2(*(const half2*)&raw[it].w);
            __stcs((float4*)(wp + idx * 8),     make_float4(f0.x * iz, f0.y * iz, f1.x * iz, f1.y * iz));
            __stcs((float4*)(wp + idx * 8) + 1, make_float4(f2.x * iz, f2.y * iz, f3.x * iz, f3.y * iz));
        }
    }
}

// ======================================================================
// Fused launch s: CTAs [0,425) run upass for strip s (buffers cur);
// CTAs [425, 2425) scale strip s-1 (buffers prv).  Launch boundary
// guarantees upass[s-1] is complete before this kernel starts.
// ======================================================================
__global__ void __launch_bounds__(256, 4) fused_kernel(
    const float* __restrict__ A, float* __restrict__ Wout,
    int row0, int row0p, int cur, int prv,
    const float* __restrict__ p_raw_alpha)
{
    if (blockIdx.x >= UCTAS) {                 // ---- scale role (strip s-1) ----
        if (row0p < 0) return;                 // first launch: nothing to scale
        scale_row(Wout, g_u[prv], g_Zpart[prv], row0p, blockIdx.x - UCTAS);
        return;
    }

    // ---- upass role (strip s) ----
    __shared__ __align__(16) ull   sHnI2[BM * EMB];      // (v,v) duplicated pairs
    __shared__ __align__(16) float sHnT[2][EMB * BN];

    const int tid   = threadIdx.x;
    const int tx    = tid & 15;
    const int ty    = tid >> 4;                          // [0,16)
    const int strip = blockIdx.x % JSTRIPS;
    const int i0    = row0 + (blockIdx.x / JSTRIPS) * BM;
    __half* ubuf    = g_u[cur];

    const float kA    = 1.f / (1.f + __expf(-p_raw_alpha[0]));   // alpha
    const ull   bias2 = f2pk(4.f, 4.f);

    for (int t = tid; t < BM * EMB; t += 256) {
        const float v = g_Hn[i0 * EMB + t];
        sHnI2[t] = f2pk(v, v);
    }

    float zacc[5] = {0.f, 0.f, 0.f, 0.f, 0.f};

    prefetch_tile(&sHnT[0][0], strip * BN);
    int buf = 0;
    for (int jt = strip; jt < NJT; jt += JSTRIPS) {
        const int nxt = jt + JSTRIPS;
        if (nxt < NJT) {
            prefetch_tile(&sHnT[buf ^ 1][0], nxt * BN);
            asm volatile("cp.async.wait_group 1;" ::: "memory");
        } else {
            asm volatile("cp.async.wait_group 0;" ::: "memory");
        }
        __syncthreads();
        const float* sT = &sHnT[buf][0];
        if (jt == NJT - 1) {
            if (tx < 4)    // last tile: 16 real cols = 4 quads
                tile_u(A, row0, ubuf, sHnI2, sT, i0, jt * BN, ty, tx, kA, bias2, zacc);
        } else {
            #pragma unroll 1
            for (int h = 0; h < 2; ++h)
                tile_u(A, row0, ubuf, sHnI2, sT + 64 * h, i0, jt * BN + 64 * h,
                       ty, tx, kA, bias2, zacc);
        }
        __syncthreads();
        buf ^= 1;
    }

    #pragma unroll
    for (int r = 0; r < 5; ++r) {
        float z = zacc[r];
        z += __shfl_xor_sync(0xffffffffu, z, 1);
        z += __shfl_xor_sync(0xffffffffu, z, 2);
        z += __shfl_xor_sync(0xffffffffu, z, 4);
        z += __shfl_xor_sync(0xffffffffu, z, 8);
        if (tx == 0) g_Zpart[cur][strip * SROWS + (i0 - row0) + ty + 16 * r] = z;
    }
}

// ======================================================================
// Final scale-only launch (strip NSTRIP-1)
// ======================================================================
__global__ void __launch_bounds__(256) scale_kernel(
    float* __restrict__ Wout, int row0p, int prv)
{
    scale_row(Wout, g_u[prv], g_Zpart[prv], row0p, blockIdx.x);
}

// ======================================================================
extern "C" void kernel_launch(void* const* d_in, const int* in_sizes, int n_in,
                              void* d_out, int out_size)
{
    (void)in_sizes; (void)n_in; (void)out_size;
    const float* X         = (const float*)d_in[0];
    const float* A         = (const float*)d_in[1];
    const float* W1        = (const float*)d_in[2];
    const float* b1        = (const float*)d_in[3];
    const float* W2        = (const float*)d_in[4];
    const float* b2        = (const float*)d_in[5];
    const float* log_tau   = (const float*)d_in[6];
    const float* raw_alpha = (const float*)d_in[7];

    float* out  = (float*)d_out;
    float* Wout = out;                                   // (N, N) first
    float* Hout = out + (size_t)N_ROWS * N_ROWS;         // (N, EMB) second

    encoder_kernel<<<NPAD / 8, 256>>>(X, W1, b1, W2, b2, Hout, log_tau, raw_alpha);

    for (int s = 0; s < NSTRIP; ++s) {
        const int row0  = s * SROWS;
        const int row0p = (s - 1) * SROWS;               // -2000 on s=0 -> scale role skips
        fused_kernel<<<TCTAS, 256>>>(A, Wout, row0, (s == 0) ? -1 : row0p,
                                     s & 1, (s - 1) & 1, raw_alpha);
    }
    scale_kernel<<<SROWS, 256>>>(Wout, (NSTRIP - 1) * SROWS, (NSTRIP - 1) & 1);
}